// round 1
// baseline (speedup 1.0000x reference)
#include <cuda_runtime.h>
#include <cuda_bf16.h>

// Unscaled, unmasked attention: O = softmax(Q K^T) V
// Shapes: [B=4, H=16, S=2048, D=64], fp32 in/out.
// Flash-attention single pass: CTA = 64 query rows of one (b,h).
// 256 threads as a 16x16 grid, 4x4 register blocking.

#define BM 64
#define BN 64
#define DH 64
#define PAD 4
#define LDSTR (DH + PAD)   // 68 floats per smem row

__global__ void __launch_bounds__(256, 2)
attn_fa_kernel(const float* __restrict__ Q, const float* __restrict__ K,
               const float* __restrict__ V, float* __restrict__ Out, int S)
{
    extern __shared__ float smem[];
    float* Qs = smem;                    // [BM][LDSTR]
    float* Ks = Qs + BM * LDSTR;         // [BN][LDSTR]  key-major, dim contiguous
    float* Vs = Ks + BN * LDSTR;         // [BN][LDSTR]  key-major, dim contiguous
    float* Ps = Vs + BN * LDSTR;         // [BM][LDSTR]  probs tile

    const int tid = threadIdx.x;
    const int tx  = tid & 15;            // 16 cols of threads
    const int ty  = tid >> 4;            // 16 rows of threads

    const long long base = (long long)blockIdx.y * (long long)S * DH;
    const float* Qg = Q + base + (long long)blockIdx.x * BM * DH;
    const float* Kg = K + base;
    const float* Vg = V + base;
    float*       Og = Out + base + (long long)blockIdx.x * BM * DH;

    // ---- load Q tile (coalesced float4) ----
    #pragma unroll
    for (int i = 0; i < 4; i++) {
        int idx = tid * 4 + i * 1024;    // 0..4095
        int r = idx >> 6, c = idx & 63;
        *(float4*)(Qs + r * LDSTR + c) = *(const float4*)(Qg + r * DH + c);
    }

    // per-thread state: 4 query rows (r = 4*ty + i), replicated across tx
    float m_i[4], l_i[4];
    float acc[4][4];                     // O fragment: rows 4*ty+i, cols 4*tx+j
    #pragma unroll
    for (int i = 0; i < 4; i++) {
        m_i[i] = -3.0e38f;
        l_i[i] = 0.0f;
        #pragma unroll
        for (int j = 0; j < 4; j++) acc[i][j] = 0.0f;
    }

    for (int kt = 0; kt < S; kt += BN) {
        __syncthreads();                 // previous PV done before overwriting K/V/P
        // ---- load K,V tiles (coalesced float4) ----
        #pragma unroll
        for (int i = 0; i < 4; i++) {
            int idx = tid * 4 + i * 1024;
            int r = idx >> 6, c = idx & 63;
            *(float4*)(Ks + r * LDSTR + c) = *(const float4*)(Kg + (long long)(kt + r) * DH + c);
            *(float4*)(Vs + r * LDSTR + c) = *(const float4*)(Vg + (long long)(kt + r) * DH + c);
        }
        __syncthreads();

        // ---- S = Q K^T : rows 4*ty+i, key-cols tx+16*j ----
        float s[4][4];
        #pragma unroll
        for (int i = 0; i < 4; i++)
            #pragma unroll
            for (int j = 0; j < 4; j++) s[i][j] = 0.0f;

        #pragma unroll 4
        for (int k = 0; k < DH; k += 4) {
            float4 q4[4], k4[4];
            #pragma unroll
            for (int i = 0; i < 4; i++)
                q4[i] = *(const float4*)(Qs + (4 * ty + i) * LDSTR + k);   // broadcast over tx
            #pragma unroll
            for (int j = 0; j < 4; j++)
                k4[j] = *(const float4*)(Ks + (tx + 16 * j) * LDSTR + k);  // 2-way max
            #pragma unroll
            for (int i = 0; i < 4; i++)
                #pragma unroll
                for (int j = 0; j < 4; j++) {
                    s[i][j] = fmaf(q4[i].x, k4[j].x, s[i][j]);
                    s[i][j] = fmaf(q4[i].y, k4[j].y, s[i][j]);
                    s[i][j] = fmaf(q4[i].z, k4[j].z, s[i][j]);
                    s[i][j] = fmaf(q4[i].w, k4[j].w, s[i][j]);
                }
        }

        // ---- online softmax (per query row, reduce across 16 tx lanes) ----
        #pragma unroll
        for (int i = 0; i < 4; i++) {
            float tmax = fmaxf(fmaxf(s[i][0], s[i][1]), fmaxf(s[i][2], s[i][3]));
            #pragma unroll
            for (int o = 8; o >= 1; o >>= 1)
                tmax = fmaxf(tmax, __shfl_xor_sync(0xffffffffu, tmax, o));

            float m_new = fmaxf(m_i[i], tmax);
            float scale = __expf(m_i[i] - m_new);
            m_i[i] = m_new;

            float tsum = 0.0f;
            #pragma unroll
            for (int j = 0; j < 4; j++) {
                float p = __expf(s[i][j] - m_new);
                s[i][j] = p;
                tsum += p;
            }
            #pragma unroll
            for (int o = 8; o >= 1; o >>= 1)
                tsum += __shfl_xor_sync(0xffffffffu, tsum, o);

            l_i[i] = l_i[i] * scale + tsum;
            #pragma unroll
            for (int j = 0; j < 4; j++) acc[i][j] *= scale;
        }

        // ---- stage P tile ----
        #pragma unroll
        for (int i = 0; i < 4; i++)
            #pragma unroll
            for (int j = 0; j < 4; j++)
                Ps[(4 * ty + i) * LDSTR + tx + 16 * j] = s[i][j];
        __syncthreads();

        // ---- O += P V : rows 4*ty+i, D-cols 4*tx+j ----
        #pragma unroll 4
        for (int k = 0; k < BN; k += 4) {
            float4 p4[4];   // p4[i] = P[row_i][k..k+3]
            float4 v4[4];   // v4[kk] = V[k+kk][4*tx..4*tx+3]
            #pragma unroll
            for (int i = 0; i < 4; i++)
                p4[i] = *(const float4*)(Ps + (4 * ty + i) * LDSTR + k);   // broadcast
            #pragma unroll
            for (int kk = 0; kk < 4; kk++)
                v4[kk] = *(const float4*)(Vs + (k + kk) * LDSTR + 4 * tx); // conflict-free
            #pragma unroll
            for (int i = 0; i < 4; i++) {
                acc[i][0] = fmaf(p4[i].x, v4[0].x, acc[i][0]);
                acc[i][1] = fmaf(p4[i].x, v4[0].y, acc[i][1]);
                acc[i][2] = fmaf(p4[i].x, v4[0].z, acc[i][2]);
                acc[i][3] = fmaf(p4[i].x, v4[0].w, acc[i][3]);
                acc[i][0] = fmaf(p4[i].y, v4[1].x, acc[i][0]);
                acc[i][1] = fmaf(p4[i].y, v4[1].y, acc[i][1]);
                acc[i][2] = fmaf(p4[i].y, v4[1].z, acc[i][2]);
                acc[i][3] = fmaf(p4[i].y, v4[1].w, acc[i][3]);
                acc[i][0] = fmaf(p4[i].z, v4[2].x, acc[i][0]);
                acc[i][1] = fmaf(p4[i].z, v4[2].y, acc[i][1]);
                acc[i][2] = fmaf(p4[i].z, v4[2].z, acc[i][2]);
                acc[i][3] = fmaf(p4[i].z, v4[2].w, acc[i][3]);
                acc[i][0] = fmaf(p4[i].w, v4[3].x, acc[i][0]);
                acc[i][1] = fmaf(p4[i].w, v4[3].y, acc[i][1]);
                acc[i][2] = fmaf(p4[i].w, v4[3].z, acc[i][2]);
                acc[i][3] = fmaf(p4[i].w, v4[3].w, acc[i][3]);
            }
        }
    }

    // ---- epilogue: normalize and store (coalesced float4) ----
    #pragma unroll
    for (int i = 0; i < 4; i++) {
        float inv = 1.0f / l_i[i];
        float4 o;
        o.x = acc[i][0] * inv;
        o.y = acc[i][1] * inv;
        o.z = acc[i][2] * inv;
        o.w = acc[i][3] * inv;
        *(float4*)(Og + (4 * ty + i) * DH + 4 * tx) = o;
    }
}

extern "C" void kernel_launch(void* const* d_in, const int* in_sizes, int n_in,
                              void* d_out, int out_size) {
    const float* Q = (const float*)d_in[0];
    const float* K = (const float*)d_in[1];
    const float* V = (const float*)d_in[2];
    float* O = (float*)d_out;

    const int S = 2048, D = 64;
    const int BH = in_sizes[0] / (S * D);   // 64

    size_t smem_bytes = (size_t)(2 * BM + 2 * BN) * LDSTR * sizeof(float); // 69632
    cudaFuncSetAttribute(attn_fa_kernel,
                         cudaFuncAttributeMaxDynamicSharedMemorySize,
                         (int)smem_bytes);

    dim3 grid(S / BM, BH);
    attn_fa_kernel<<<grid, 256, smem_bytes>>>(Q, K, V, O, S);
}

// round 4
// speedup vs baseline: 3.6603x; 3.6603x over previous
#include <cuda_runtime.h>
#include <cuda_fp16.h>
#include <cstdint>

// Attention O = softmax(QK^T)V, [B=4,H=16,S=2048,D=64], fp32.
// Legacy tensor path (compute_103-safe): mma.sync.m16n8k16 fp16, 3-pass hi/lo QK^T,
// single-pass PV, FA2 register-resident P, online softmax.

#define S_LEN 2048
#define DHD 64
#define BM 128
#define BN 64
#define NT (S_LEN / BN)     // 32
#define STR 72              // smem row stride in halfs (bank-conflict-free for ldmatrix)

// smem offsets (in halfs)
#define O_QH 0
#define O_QL (BM * STR)
#define O_KH (2 * BM * STR)
#define O_KL (2 * BM * STR + BN * STR)
#define O_VT (2 * BM * STR + 2 * BN * STR)
#define SMEM_HALFS (2 * BM * STR + 3 * BN * STR)
#define SMEM_BYTES (SMEM_HALFS * 2)   // 64512

static __device__ __forceinline__ uint32_t sa(const void* p) {
    uint32_t a;
    asm("{\n\t.reg .u64 t;\n\tcvta.to.shared.u64 t, %1;\n\tcvt.u32.u64 %0, t;\n\t}"
        : "=r"(a) : "l"(p));
    return a;
}
static __device__ __forceinline__ void ldx4(uint32_t* r, uint32_t a) {
    asm volatile("ldmatrix.sync.aligned.m8n8.x4.shared.b16 {%0,%1,%2,%3}, [%4];"
                 : "=r"(r[0]), "=r"(r[1]), "=r"(r[2]), "=r"(r[3]) : "r"(a));
}
static __device__ __forceinline__ void ldx2(uint32_t* r, uint32_t a) {
    asm volatile("ldmatrix.sync.aligned.m8n8.x2.shared.b16 {%0,%1}, [%2];"
                 : "=r"(r[0]), "=r"(r[1]) : "r"(a));
}
static __device__ __forceinline__ void mma16816(float* d, const uint32_t* a, const uint32_t* b) {
    asm volatile("mma.sync.aligned.m16n8k16.row.col.f32.f16.f16.f32 "
                 "{%0,%1,%2,%3},{%4,%5,%6,%7},{%8,%9},{%0,%1,%2,%3};"
                 : "+f"(d[0]), "+f"(d[1]), "+f"(d[2]), "+f"(d[3])
                 : "r"(a[0]), "r"(a[1]), "r"(a[2]), "r"(a[3]), "r"(b[0]), "r"(b[1]));
}
// split (a,b) into packed hi half2 and residual-lo half2
static __device__ __forceinline__ void split2(float a, float b, uint32_t& hi, uint32_t& lo) {
    __half ha = __float2half_rn(a), hb = __float2half_rn(b);
    __half2 h = __halves2half2(ha, hb);
    __half2 l = __floats2half2_rn(a - __half2float(ha), b - __half2float(hb));
    hi = *(uint32_t*)&h;
    lo = *(uint32_t*)&l;
}

__global__ void __launch_bounds__(256, 2)
attn_mma_kernel(const float* __restrict__ Q, const float* __restrict__ K,
                const float* __restrict__ V, float* __restrict__ Out)
{
    extern __shared__ __half sm[];
    const uint32_t sb = sa(sm);

    const int tid  = threadIdx.x;
    const int wid  = tid >> 5;
    const int lane = tid & 31;
    const int l15  = lane & 15;

    const long long base = (long long)blockIdx.y * (S_LEN * DHD);
    const float* Qg = Q + base + (long long)blockIdx.x * (BM * DHD);
    const float* Kg = K + base;
    const float* Vg = V + base;
    float*       Og = Out + base + (long long)blockIdx.x * (BM * DHD);

    // ---- Q tile: load, hi/lo fp16 split -> smem ----
    #pragma unroll
    for (int i = 0; i < 8; i++) {
        int idx = tid * 4 + i * 1024;     // 0..8191
        int r = idx >> 6, c = idx & 63;
        float4 q = *(const float4*)(Qg + r * DHD + c);
        uint32_t h0, l0, h1, l1;
        split2(q.x, q.y, h0, l0);
        split2(q.z, q.w, h1, l1);
        *(uint32_t*)(&sm[O_QH + r * STR + c])     = h0;
        *(uint32_t*)(&sm[O_QH + r * STR + c + 2]) = h1;
        *(uint32_t*)(&sm[O_QL + r * STR + c])     = l0;
        *(uint32_t*)(&sm[O_QL + r * STR + c + 2]) = l1;
    }

    float o[8][4];
    #pragma unroll
    for (int nn = 0; nn < 8; nn++)
        #pragma unroll
        for (int j = 0; j < 4; j++) o[nn][j] = 0.0f;
    float m_lo = -1.0e30f, m_hi = -1.0e30f, l_lo = 0.0f, l_hi = 0.0f;

    const int vkey = tid >> 4;            // 0..15
    const int vd   = (tid & 15) * 4;      // d segment

    for (int t = 0; t < NT; t++) {
        const int kt = t * BN;

        // ---- gmem loads into regs (overlap with prior compute) ----
        float4 kreg[4], vreg[4];
        #pragma unroll
        for (int i = 0; i < 4; i++) {
            int idx = tid * 4 + i * 1024; // 0..4095
            int r = idx >> 6, c = idx & 63;
            kreg[i] = *(const float4*)(Kg + (long long)(kt + r) * DHD + c);
            vreg[i] = *(const float4*)(Vg + (long long)(kt + vkey + i * 16) * DHD + vd);
        }
        __syncthreads();                  // prior tile's smem reads done

        // ---- K hi/lo -> smem ----
        #pragma unroll
        for (int i = 0; i < 4; i++) {
            int idx = tid * 4 + i * 1024;
            int r = idx >> 6, c = idx & 63;
            uint32_t h0, l0, h1, l1;
            split2(kreg[i].x, kreg[i].y, h0, l0);
            split2(kreg[i].z, kreg[i].w, h1, l1);
            *(uint32_t*)(&sm[O_KH + r * STR + c])     = h0;
            *(uint32_t*)(&sm[O_KH + r * STR + c + 2]) = h1;
            *(uint32_t*)(&sm[O_KL + r * STR + c])     = l0;
            *(uint32_t*)(&sm[O_KL + r * STR + c + 2]) = l1;
        }
        // ---- V transpose -> Vt[d][key] fp16 ----
        #pragma unroll
        for (int i = 0; i < 4; i++) {
            int key = vkey + i * 16;
            sm[O_VT + (vd + 0) * STR + key] = __float2half_rn(vreg[i].x);
            sm[O_VT + (vd + 1) * STR + key] = __float2half_rn(vreg[i].y);
            sm[O_VT + (vd + 2) * STR + key] = __float2half_rn(vreg[i].z);
            sm[O_VT + (vd + 3) * STR + key] = __float2half_rn(vreg[i].w);
        }
        __syncthreads();

        // ---- QK^T: 3-pass hi/lo (QhKh + QlKh + QhKl) ----
        float s[8][4];
        #pragma unroll
        for (int nn = 0; nn < 8; nn++)
            #pragma unroll
            for (int j = 0; j < 4; j++) s[nn][j] = 0.0f;

        #pragma unroll
        for (int kk = 0; kk < 4; kk++) {
            const int ar = wid * 16 + (lane & 7) + ((lane >> 3) & 1) * 8;
            const int ac = kk * 16 + (lane >> 4) * 8;
            uint32_t ah[4], al[4];
            ldx4(ah, sb + (uint32_t)(O_QH + ar * STR + ac) * 2);
            ldx4(al, sb + (uint32_t)(O_QL + ar * STR + ac) * 2);
            const int bro = (l15 & 7);
            const int bc  = kk * 16 + ((l15 >> 3) & 1) * 8;
            #pragma unroll
            for (int nn = 0; nn < 8; nn++) {
                uint32_t bh[2], bl[2];
                ldx2(bh, sb + (uint32_t)(O_KH + (nn * 8 + bro) * STR + bc) * 2);
                ldx2(bl, sb + (uint32_t)(O_KL + (nn * 8 + bro) * STR + bc) * 2);
                mma16816(s[nn], ah, bh);
                mma16816(s[nn], al, bh);
                mma16816(s[nn], ah, bl);
            }
        }

        // ---- online softmax (rows: lo = lane>>2, hi = +8) ----
        float mt_lo = -1.0e30f, mt_hi = -1.0e30f;
        #pragma unroll
        for (int nn = 0; nn < 8; nn++) {
            mt_lo = fmaxf(mt_lo, fmaxf(s[nn][0], s[nn][1]));
            mt_hi = fmaxf(mt_hi, fmaxf(s[nn][2], s[nn][3]));
        }
        mt_lo = fmaxf(mt_lo, __shfl_xor_sync(0xffffffffu, mt_lo, 1));
        mt_lo = fmaxf(mt_lo, __shfl_xor_sync(0xffffffffu, mt_lo, 2));
        mt_hi = fmaxf(mt_hi, __shfl_xor_sync(0xffffffffu, mt_hi, 1));
        mt_hi = fmaxf(mt_hi, __shfl_xor_sync(0xffffffffu, mt_hi, 2));

        const float mn_lo = fmaxf(m_lo, mt_lo);
        const float mn_hi = fmaxf(m_hi, mt_hi);
        const float sc_lo = __expf(m_lo - mn_lo);
        const float sc_hi = __expf(m_hi - mn_hi);
        m_lo = mn_lo; m_hi = mn_hi;
        l_lo *= sc_lo; l_hi *= sc_hi;

        uint32_t pa[8], pb[8];
        #pragma unroll
        for (int nn = 0; nn < 8; nn++) {
            float p0 = __expf(s[nn][0] - mn_lo);
            float p1 = __expf(s[nn][1] - mn_lo);
            float p2 = __expf(s[nn][2] - mn_hi);
            float p3 = __expf(s[nn][3] - mn_hi);
            l_lo += p0 + p1;
            l_hi += p2 + p3;
            __half2 hA = __floats2half2_rn(p0, p1);
            __half2 hB = __floats2half2_rn(p2, p3);
            pa[nn] = *(uint32_t*)&hA;
            pb[nn] = *(uint32_t*)&hB;
            o[nn][0] *= sc_lo; o[nn][1] *= sc_lo;
            o[nn][2] *= sc_hi; o[nn][3] *= sc_hi;
        }

        // ---- PV: O += P * Vt^T (A = P frags in regs) ----
        #pragma unroll
        for (int kk = 0; kk < 4; kk++) {
            uint32_t a[4] = { pa[2 * kk], pb[2 * kk], pa[2 * kk + 1], pb[2 * kk + 1] };
            const int bro = (l15 & 7);
            const int bc  = kk * 16 + ((l15 >> 3) & 1) * 8;
            #pragma unroll
            for (int nn = 0; nn < 8; nn++) {
                uint32_t bv[2];
                ldx2(bv, sb + (uint32_t)(O_VT + (nn * 8 + bro) * STR + bc) * 2);
                mma16816(o[nn], a, bv);
            }
        }
    }

    // ---- epilogue: reduce l across lane%4, normalize, store ----
    l_lo += __shfl_xor_sync(0xffffffffu, l_lo, 1);
    l_lo += __shfl_xor_sync(0xffffffffu, l_lo, 2);
    l_hi += __shfl_xor_sync(0xffffffffu, l_hi, 1);
    l_hi += __shfl_xor_sync(0xffffffffu, l_hi, 2);
    const float inv_lo = 1.0f / l_lo;
    const float inv_hi = 1.0f / l_hi;

    const int r_lo = wid * 16 + (lane >> 2);
    const int r_hi = r_lo + 8;
    #pragma unroll
    for (int nn = 0; nn < 8; nn++) {
        int d0 = nn * 8 + (lane & 3) * 2;
        float2 wlo = { o[nn][0] * inv_lo, o[nn][1] * inv_lo };
        float2 whi = { o[nn][2] * inv_hi, o[nn][3] * inv_hi };
        *(float2*)(Og + (long long)r_lo * DHD + d0) = wlo;
        *(float2*)(Og + (long long)r_hi * DHD + d0) = whi;
    }
}

extern "C" void kernel_launch(void* const* d_in, const int* in_sizes, int n_in,
                              void* d_out, int out_size) {
    const float* Q = (const float*)d_in[0];
    const float* K = (const float*)d_in[1];
    const float* V = (const float*)d_in[2];
    float* O = (float*)d_out;

    const int BH = in_sizes[0] / (S_LEN * DHD);  // 64

    cudaFuncSetAttribute(attn_mma_kernel,
                         cudaFuncAttributeMaxDynamicSharedMemorySize, SMEM_BYTES);
    dim3 grid(S_LEN / BM, BH);
    attn_mma_kernel<<<grid, 256, SMEM_BYTES>>>(Q, K, V, O);
}

// round 6
// speedup vs baseline: 4.4745x; 1.2224x over previous
#include <cuda_runtime.h>
#include <cuda_fp16.h>
#include <cstdint>

// Attention O = softmax(QK^T)V, [B=4,H=16,S=2048,D=64], fp32.
// mma.sync.m16n8k16 fp16, 3-pass hi/lo QK^T, single-pass PV.
// R5: V stored PLAIN [key][d] in smem; PV B-frags via ldmatrix.x2.trans
//     (kills the 8-way-conflicted V-transpose STS of R4).

#define S_LEN 2048
#define DHD 64
#define BM 128
#define BN 64
#define NT (S_LEN / BN)     // 32
#define STR 72              // smem row stride in halfs

// smem offsets (in halfs)
#define O_QH 0
#define O_QL (BM * STR)
#define O_KH (2 * BM * STR)
#define O_KL (2 * BM * STR + BN * STR)
#define O_VS (2 * BM * STR + 2 * BN * STR)
#define SMEM_HALFS (2 * BM * STR + 3 * BN * STR)
#define SMEM_BYTES (SMEM_HALFS * 2)   // 64512

static __device__ __forceinline__ uint32_t sa(const void* p) {
    uint32_t a;
    asm("{\n\t.reg .u64 t;\n\tcvta.to.shared.u64 t, %1;\n\tcvt.u32.u64 %0, t;\n\t}"
        : "=r"(a) : "l"(p));
    return a;
}
static __device__ __forceinline__ void ldx4(uint32_t* r, uint32_t a) {
    asm volatile("ldmatrix.sync.aligned.m8n8.x4.shared.b16 {%0,%1,%2,%3}, [%4];"
                 : "=r"(r[0]), "=r"(r[1]), "=r"(r[2]), "=r"(r[3]) : "r"(a));
}
static __device__ __forceinline__ void ldx2(uint32_t* r, uint32_t a) {
    asm volatile("ldmatrix.sync.aligned.m8n8.x2.shared.b16 {%0,%1}, [%2];"
                 : "=r"(r[0]), "=r"(r[1]) : "r"(a));
}
static __device__ __forceinline__ void ldx2t(uint32_t* r, uint32_t a) {
    asm volatile("ldmatrix.sync.aligned.m8n8.x2.trans.shared.b16 {%0,%1}, [%2];"
                 : "=r"(r[0]), "=r"(r[1]) : "r"(a));
}
static __device__ __forceinline__ void mma16816(float* d, const uint32_t* a, const uint32_t* b) {
    asm volatile("mma.sync.aligned.m16n8k16.row.col.f32.f16.f16.f32 "
                 "{%0,%1,%2,%3},{%4,%5,%6,%7},{%8,%9},{%0,%1,%2,%3};"
                 : "+f"(d[0]), "+f"(d[1]), "+f"(d[2]), "+f"(d[3])
                 : "r"(a[0]), "r"(a[1]), "r"(a[2]), "r"(a[3]), "r"(b[0]), "r"(b[1]));
}
// split (a,b) into packed hi half2 and residual-lo half2
static __device__ __forceinline__ void split2(float a, float b, uint32_t& hi, uint32_t& lo) {
    __half ha = __float2half_rn(a), hb = __float2half_rn(b);
    __half2 h = __halves2half2(ha, hb);
    __half2 l = __floats2half2_rn(a - __half2float(ha), b - __half2float(hb));
    hi = *(uint32_t*)&h;
    lo = *(uint32_t*)&l;
}

__global__ void __launch_bounds__(256, 2)
attn_mma_kernel(const float* __restrict__ Q, const float* __restrict__ K,
                const float* __restrict__ V, float* __restrict__ Out)
{
    extern __shared__ __half sm[];
    const uint32_t sb = sa(sm);

    const int tid  = threadIdx.x;
    const int wid  = tid >> 5;
    const int lane = tid & 31;
    const int l15  = lane & 15;

    const long long base = (long long)blockIdx.y * (S_LEN * DHD);
    const float* Qg = Q + base + (long long)blockIdx.x * (BM * DHD);
    const float* Kg = K + base;
    const float* Vg = V + base;
    float*       Og = Out + base + (long long)blockIdx.x * (BM * DHD);

    // ---- Q tile: load, hi/lo fp16 split -> smem ----
    #pragma unroll
    for (int i = 0; i < 8; i++) {
        int idx = tid * 4 + i * 1024;     // 0..8191
        int r = idx >> 6, c = idx & 63;
        float4 q = *(const float4*)(Qg + r * DHD + c);
        uint32_t h0, l0, h1, l1;
        split2(q.x, q.y, h0, l0);
        split2(q.z, q.w, h1, l1);
        *(uint32_t*)(&sm[O_QH + r * STR + c])     = h0;
        *(uint32_t*)(&sm[O_QH + r * STR + c + 2]) = h1;
        *(uint32_t*)(&sm[O_QL + r * STR + c])     = l0;
        *(uint32_t*)(&sm[O_QL + r * STR + c + 2]) = l1;
    }

    float o[8][4];
    #pragma unroll
    for (int nn = 0; nn < 8; nn++)
        #pragma unroll
        for (int j = 0; j < 4; j++) o[nn][j] = 0.0f;
    float m_lo = -1.0e30f, m_hi = -1.0e30f, l_lo = 0.0f, l_hi = 0.0f;

    for (int t = 0; t < NT; t++) {
        const int kt = t * BN;

        // ---- gmem loads into regs (overlap with prior compute) ----
        float4 kreg[4], vreg[4];
        #pragma unroll
        for (int i = 0; i < 4; i++) {
            int idx = tid * 4 + i * 1024; // 0..4095
            int r = idx >> 6, c = idx & 63;
            kreg[i] = *(const float4*)(Kg + (long long)(kt + r) * DHD + c);
            vreg[i] = *(const float4*)(Vg + (long long)(kt + r) * DHD + c);
        }
        __syncthreads();                  // prior tile's smem reads done

        // ---- K hi/lo + V plain -> smem ----
        #pragma unroll
        for (int i = 0; i < 4; i++) {
            int idx = tid * 4 + i * 1024;
            int r = idx >> 6, c = idx & 63;
            uint32_t h0, l0, h1, l1;
            split2(kreg[i].x, kreg[i].y, h0, l0);
            split2(kreg[i].z, kreg[i].w, h1, l1);
            *(uint32_t*)(&sm[O_KH + r * STR + c])     = h0;
            *(uint32_t*)(&sm[O_KH + r * STR + c + 2]) = h1;
            *(uint32_t*)(&sm[O_KL + r * STR + c])     = l0;
            *(uint32_t*)(&sm[O_KL + r * STR + c + 2]) = l1;
            __half2 v0 = __floats2half2_rn(vreg[i].x, vreg[i].y);
            __half2 v1 = __floats2half2_rn(vreg[i].z, vreg[i].w);
            *(uint32_t*)(&sm[O_VS + r * STR + c])     = *(uint32_t*)&v0;
            *(uint32_t*)(&sm[O_VS + r * STR + c + 2]) = *(uint32_t*)&v1;
        }
        __syncthreads();

        // ---- QK^T: 3-pass hi/lo (QhKh + QlKh + QhKl) ----
        float s[8][4];
        #pragma unroll
        for (int nn = 0; nn < 8; nn++)
            #pragma unroll
            for (int j = 0; j < 4; j++) s[nn][j] = 0.0f;

        #pragma unroll
        for (int kk = 0; kk < 4; kk++) {
            const int ar = wid * 16 + (lane & 7) + ((lane >> 3) & 1) * 8;
            const int ac = kk * 16 + (lane >> 4) * 8;
            uint32_t ah[4], al[4];
            ldx4(ah, sb + (uint32_t)(O_QH + ar * STR + ac) * 2);
            ldx4(al, sb + (uint32_t)(O_QL + ar * STR + ac) * 2);
            const int bro = (l15 & 7);
            const int bc  = kk * 16 + ((l15 >> 3) & 1) * 8;
            #pragma unroll
            for (int nn = 0; nn < 8; nn++) {
                uint32_t bh[2], bl[2];
                ldx2(bh, sb + (uint32_t)(O_KH + (nn * 8 + bro) * STR + bc) * 2);
                ldx2(bl, sb + (uint32_t)(O_KL + (nn * 8 + bro) * STR + bc) * 2);
                mma16816(s[nn], ah, bh);
                mma16816(s[nn], al, bh);
                mma16816(s[nn], ah, bl);
            }
        }

        // ---- online softmax (rows: lo = lane>>2, hi = +8) ----
        float mt_lo = -1.0e30f, mt_hi = -1.0e30f;
        #pragma unroll
        for (int nn = 0; nn < 8; nn++) {
            mt_lo = fmaxf(mt_lo, fmaxf(s[nn][0], s[nn][1]));
            mt_hi = fmaxf(mt_hi, fmaxf(s[nn][2], s[nn][3]));
        }
        mt_lo = fmaxf(mt_lo, __shfl_xor_sync(0xffffffffu, mt_lo, 1));
        mt_lo = fmaxf(mt_lo, __shfl_xor_sync(0xffffffffu, mt_lo, 2));
        mt_hi = fmaxf(mt_hi, __shfl_xor_sync(0xffffffffu, mt_hi, 1));
        mt_hi = fmaxf(mt_hi, __shfl_xor_sync(0xffffffffu, mt_hi, 2));

        const float mn_lo = fmaxf(m_lo, mt_lo);
        const float mn_hi = fmaxf(m_hi, mt_hi);
        const float sc_lo = __expf(m_lo - mn_lo);
        const float sc_hi = __expf(m_hi - mn_hi);
        m_lo = mn_lo; m_hi = mn_hi;
        l_lo *= sc_lo; l_hi *= sc_hi;

        uint32_t pa[8], pb[8];
        #pragma unroll
        for (int nn = 0; nn < 8; nn++) {
            float p0 = __expf(s[nn][0] - mn_lo);
            float p1 = __expf(s[nn][1] - mn_lo);
            float p2 = __expf(s[nn][2] - mn_hi);
            float p3 = __expf(s[nn][3] - mn_hi);
            l_lo += p0 + p1;
            l_hi += p2 + p3;
            __half2 hA = __floats2half2_rn(p0, p1);
            __half2 hB = __floats2half2_rn(p2, p3);
            pa[nn] = *(uint32_t*)&hA;
            pb[nn] = *(uint32_t*)&hB;
            o[nn][0] *= sc_lo; o[nn][1] *= sc_lo;
            o[nn][2] *= sc_hi; o[nn][3] *= sc_hi;
        }

        // ---- PV: O += P * V (B frags via ldmatrix.trans on plain V[key][d]) ----
        #pragma unroll
        for (int kk = 0; kk < 4; kk++) {
            uint32_t a[4] = { pa[2 * kk], pb[2 * kk], pa[2 * kk + 1], pb[2 * kk + 1] };
            #pragma unroll
            for (int nn = 0; nn < 8; nn++) {
                uint32_t bv[2];
                ldx2t(bv, sb + (uint32_t)(O_VS + (kk * 16 + l15) * STR + nn * 8) * 2);
                mma16816(o[nn], a, bv);
            }
        }
    }

    // ---- epilogue: reduce l across lane%4, normalize, store ----
    l_lo += __shfl_xor_sync(0xffffffffu, l_lo, 1);
    l_lo += __shfl_xor_sync(0xffffffffu, l_lo, 2);
    l_hi += __shfl_xor_sync(0xffffffffu, l_hi, 1);
    l_hi += __shfl_xor_sync(0xffffffffu, l_hi, 2);
    const float inv_lo = 1.0f / l_lo;
    const float inv_hi = 1.0f / l_hi;

    const int r_lo = wid * 16 + (lane >> 2);
    const int r_hi = r_lo + 8;
    #pragma unroll
    for (int nn = 0; nn < 8; nn++) {
        int d0 = nn * 8 + (lane & 3) * 2;
        float2 wlo = { o[nn][0] * inv_lo, o[nn][1] * inv_lo };
        float2 whi = { o[nn][2] * inv_hi, o[nn][3] * inv_hi };
        *(float2*)(Og + (long long)r_lo * DHD + d0) = wlo;
        *(float2*)(Og + (long long)r_hi * DHD + d0) = whi;
    }
}

extern "C" void kernel_launch(void* const* d_in, const int* in_sizes, int n_in,
                              void* d_out, int out_size) {
    const float* Q = (const float*)d_in[0];
    const float* K = (const float*)d_in[1];
    const float* V = (const float*)d_in[2];
    float* O = (float*)d_out;

    const int BH = in_sizes[0] / (S_LEN * DHD);  // 64

    cudaFuncSetAttribute(attn_mma_kernel,
                         cudaFuncAttributeMaxDynamicSharedMemorySize, SMEM_BYTES);
    dim3 grid(S_LEN / BM, BH);
    attn_mma_kernel<<<grid, 256, SMEM_BYTES>>>(Q, K, V, O);
}

// round 7
// speedup vs baseline: 4.6742x; 1.0446x over previous
#include <cuda_runtime.h>
#include <cuda_fp16.h>
#include <cstdint>

// Attention O = softmax(QK^T)V, [B=4,H=16,S=2048,D=64], fp32.
// R6: K/V preconverted once to fp16 hi/lo in __device__ scratch; main kernel
// streams tiles via cp.async into double-buffered smem (1 sync/tile).
// QK^T = 3-pass fp16 hi/lo, PV single-pass (ldmatrix.trans on plain V).

#define S_LEN 2048
#define DHD 64
#define BM 128
#define BN 64
#define NT (S_LEN / BN)     // 32
#define STR 72              // smem row stride in halfs
#define TOTE (64LL * S_LEN * DHD)   // elements per tensor (BH=64)

// smem offsets (halfs)
#define O_QH 0
#define O_QL (BM * STR)                 // 9216
#define O_B0 (2 * BM * STR)             // 18432
#define BUFH (3 * BN * STR)             // 13824 halfs per buffer (KH,KL,VS)
#define SMEM_HALFS (O_B0 + 2 * BUFH)    // 46080
#define SMEM_BYTES (SMEM_HALFS * 2)     // 92160

__device__ __half g_KH[TOTE];
__device__ __half g_KL[TOTE];
__device__ __half g_VS[TOTE];

static __device__ __forceinline__ uint32_t sa(const void* p) {
    uint32_t a;
    asm("{\n\t.reg .u64 t;\n\tcvta.to.shared.u64 t, %1;\n\tcvt.u32.u64 %0, t;\n\t}"
        : "=r"(a) : "l"(p));
    return a;
}
static __device__ __forceinline__ void ldx4(uint32_t* r, uint32_t a) {
    asm volatile("ldmatrix.sync.aligned.m8n8.x4.shared.b16 {%0,%1,%2,%3}, [%4];"
                 : "=r"(r[0]), "=r"(r[1]), "=r"(r[2]), "=r"(r[3]) : "r"(a));
}
static __device__ __forceinline__ void ldx2(uint32_t* r, uint32_t a) {
    asm volatile("ldmatrix.sync.aligned.m8n8.x2.shared.b16 {%0,%1}, [%2];"
                 : "=r"(r[0]), "=r"(r[1]) : "r"(a));
}
static __device__ __forceinline__ void ldx2t(uint32_t* r, uint32_t a) {
    asm volatile("ldmatrix.sync.aligned.m8n8.x2.trans.shared.b16 {%0,%1}, [%2];"
                 : "=r"(r[0]), "=r"(r[1]) : "r"(a));
}
static __device__ __forceinline__ void mma16816(float* d, const uint32_t* a, const uint32_t* b) {
    asm volatile("mma.sync.aligned.m16n8k16.row.col.f32.f16.f16.f32 "
                 "{%0,%1,%2,%3},{%4,%5,%6,%7},{%8,%9},{%0,%1,%2,%3};"
                 : "+f"(d[0]), "+f"(d[1]), "+f"(d[2]), "+f"(d[3])
                 : "r"(a[0]), "r"(a[1]), "r"(a[2]), "r"(a[3]), "r"(b[0]), "r"(b[1]));
}
static __device__ __forceinline__ void cpasync16(uint32_t dst, const void* src) {
    asm volatile("cp.async.cg.shared.global [%0], [%1], 16;" :: "r"(dst), "l"(src) : "memory");
}
#define CP_COMMIT() asm volatile("cp.async.commit_group;" ::: "memory")
#define CP_WAIT0()  asm volatile("cp.async.wait_group 0;" ::: "memory")

// split (a,b) into packed hi half2 and residual-lo half2
static __device__ __forceinline__ void split2(float a, float b, uint32_t& hi, uint32_t& lo) {
    __half ha = __float2half_rn(a), hb = __float2half_rn(b);
    __half2 h = __halves2half2(ha, hb);
    __half2 l = __floats2half2_rn(a - __half2float(ha), b - __half2float(hb));
    hi = *(uint32_t*)&h;
    lo = *(uint32_t*)&l;
}

// ---- pass 1: K,V fp32 -> fp16 hi/lo scratch ----
__global__ void __launch_bounds__(256)
preconv_kernel(const float* __restrict__ K, const float* __restrict__ V) {
    long long i4 = ((long long)blockIdx.x * 256 + threadIdx.x) * 4;
    if (i4 >= TOTE) return;
    float4 k4 = *(const float4*)(K + i4);
    float4 v4 = *(const float4*)(V + i4);
    uint32_t h0, l0, h1, l1;
    split2(k4.x, k4.y, h0, l0);
    split2(k4.z, k4.w, h1, l1);
    *(uint32_t*)(g_KH + i4)     = h0;
    *(uint32_t*)(g_KH + i4 + 2) = h1;
    *(uint32_t*)(g_KL + i4)     = l0;
    *(uint32_t*)(g_KL + i4 + 2) = l1;
    __half2 va = __floats2half2_rn(v4.x, v4.y);
    __half2 vb = __floats2half2_rn(v4.z, v4.w);
    *(uint32_t*)(g_VS + i4)     = *(uint32_t*)&va;
    *(uint32_t*)(g_VS + i4 + 2) = *(uint32_t*)&vb;
}

// ---- pass 2: flash attention ----
__global__ void __launch_bounds__(256, 2)
attn_mma_kernel(const float* __restrict__ Q, float* __restrict__ Out)
{
    extern __shared__ __half sm[];
    const uint32_t sb = sa(sm);

    const int tid  = threadIdx.x;
    const int wid  = tid >> 5;
    const int lane = tid & 31;
    const int l15  = lane & 15;

    const long long base = (long long)blockIdx.y * (S_LEN * DHD);
    const float*  Qg  = Q + base + (long long)blockIdx.x * (BM * DHD);
    const __half* KHg = g_KH + base;
    const __half* KLg = g_KL + base;
    const __half* VSg = g_VS + base;
    float*        Og  = Out + base + (long long)blockIdx.x * (BM * DHD);

    // cp.async chunk mapping: 2 chunks per thread per matrix (512 chunks each)
    const int c0r = tid >> 3, c0c = (tid & 7) * 8;          // chunk tid
    const int c1r = (tid + 256) >> 3, c1c = c0c;            // chunk tid+256

    // ---- prologue: issue tile-0 copies, then convert Q ----
    {
        const __half* k0 = KHg;  // kt = 0
        uint32_t bk = sb + (uint32_t)(O_B0) * 2;
        cpasync16(bk + (uint32_t)(c0r * STR + c0c) * 2, KHg + c0r * DHD + c0c);
        cpasync16(bk + (uint32_t)(c1r * STR + c1c) * 2, KHg + c1r * DHD + c1c);
        bk += BN * STR * 2;
        cpasync16(bk + (uint32_t)(c0r * STR + c0c) * 2, KLg + c0r * DHD + c0c);
        cpasync16(bk + (uint32_t)(c1r * STR + c1c) * 2, KLg + c1r * DHD + c1c);
        bk += BN * STR * 2;
        cpasync16(bk + (uint32_t)(c0r * STR + c0c) * 2, VSg + c0r * DHD + c0c);
        cpasync16(bk + (uint32_t)(c1r * STR + c1c) * 2, VSg + c1r * DHD + c1c);
        CP_COMMIT();
        (void)k0;
    }

    #pragma unroll
    for (int i = 0; i < 8; i++) {
        int idx = tid * 4 + i * 1024;     // 0..8191
        int r = idx >> 6, c = idx & 63;
        float4 q = *(const float4*)(Qg + r * DHD + c);
        uint32_t h0, l0, h1, l1;
        split2(q.x, q.y, h0, l0);
        split2(q.z, q.w, h1, l1);
        *(uint32_t*)(&sm[O_QH + r * STR + c])     = h0;
        *(uint32_t*)(&sm[O_QH + r * STR + c + 2]) = h1;
        *(uint32_t*)(&sm[O_QL + r * STR + c])     = l0;
        *(uint32_t*)(&sm[O_QL + r * STR + c + 2]) = l1;
    }

    float o[8][4];
    #pragma unroll
    for (int nn = 0; nn < 8; nn++)
        #pragma unroll
        for (int j = 0; j < 4; j++) o[nn][j] = 0.0f;
    float m_lo = -1.0e30f, m_hi = -1.0e30f, l_lo = 0.0f, l_hi = 0.0f;

    for (int t = 0; t < NT; t++) {
        CP_WAIT0();            // tile t landed (only group outstanding)
        __syncthreads();       // collective: tile t visible; all warps done with other buffer

        // issue tile t+1 into the other buffer (overlaps compute below)
        if (t + 1 < NT) {
            const long long kg = (long long)(t + 1) * BN * DHD;
            uint32_t bk = sb + (uint32_t)(O_B0 + ((t + 1) & 1) * BUFH) * 2;
            cpasync16(bk + (uint32_t)(c0r * STR + c0c) * 2, KHg + kg + c0r * DHD + c0c);
            cpasync16(bk + (uint32_t)(c1r * STR + c1c) * 2, KHg + kg + c1r * DHD + c1c);
            bk += BN * STR * 2;
            cpasync16(bk + (uint32_t)(c0r * STR + c0c) * 2, KLg + kg + c0r * DHD + c0c);
            cpasync16(bk + (uint32_t)(c1r * STR + c1c) * 2, KLg + kg + c1r * DHD + c1c);
            bk += BN * STR * 2;
            cpasync16(bk + (uint32_t)(c0r * STR + c0c) * 2, VSg + kg + c0r * DHD + c0c);
            cpasync16(bk + (uint32_t)(c1r * STR + c1c) * 2, VSg + kg + c1r * DHD + c1c);
            CP_COMMIT();
        }

        const int kh = O_B0 + (t & 1) * BUFH;
        const int kl = kh + BN * STR;
        const int vs = kl + BN * STR;

        // ---- QK^T: 3-pass hi/lo (QhKh + QlKh + QhKl) ----
        float s[8][4];
        #pragma unroll
        for (int nn = 0; nn < 8; nn++)
            #pragma unroll
            for (int j = 0; j < 4; j++) s[nn][j] = 0.0f;

        #pragma unroll
        for (int kk = 0; kk < 4; kk++) {
            const int ar = wid * 16 + (lane & 7) + ((lane >> 3) & 1) * 8;
            const int ac = kk * 16 + (lane >> 4) * 8;
            uint32_t ah[4], al[4];
            ldx4(ah, sb + (uint32_t)(O_QH + ar * STR + ac) * 2);
            ldx4(al, sb + (uint32_t)(O_QL + ar * STR + ac) * 2);
            const int bro = (l15 & 7);
            const int bc  = kk * 16 + ((l15 >> 3) & 1) * 8;
            #pragma unroll
            for (int nn = 0; nn < 8; nn++) {
                uint32_t bh[2], bl[2];
                ldx2(bh, sb + (uint32_t)(kh + (nn * 8 + bro) * STR + bc) * 2);
                ldx2(bl, sb + (uint32_t)(kl + (nn * 8 + bro) * STR + bc) * 2);
                mma16816(s[nn], ah, bh);
                mma16816(s[nn], al, bh);
                mma16816(s[nn], ah, bl);
            }
        }

        // ---- online softmax (rows: lo = lane>>2, hi = +8) ----
        float mt_lo = -1.0e30f, mt_hi = -1.0e30f;
        #pragma unroll
        for (int nn = 0; nn < 8; nn++) {
            mt_lo = fmaxf(mt_lo, fmaxf(s[nn][0], s[nn][1]));
            mt_hi = fmaxf(mt_hi, fmaxf(s[nn][2], s[nn][3]));
        }
        mt_lo = fmaxf(mt_lo, __shfl_xor_sync(0xffffffffu, mt_lo, 1));
        mt_lo = fmaxf(mt_lo, __shfl_xor_sync(0xffffffffu, mt_lo, 2));
        mt_hi = fmaxf(mt_hi, __shfl_xor_sync(0xffffffffu, mt_hi, 1));
        mt_hi = fmaxf(mt_hi, __shfl_xor_sync(0xffffffffu, mt_hi, 2));

        const float mn_lo = fmaxf(m_lo, mt_lo);
        const float mn_hi = fmaxf(m_hi, mt_hi);
        const float sc_lo = __expf(m_lo - mn_lo);
        const float sc_hi = __expf(m_hi - mn_hi);
        m_lo = mn_lo; m_hi = mn_hi;
        l_lo *= sc_lo; l_hi *= sc_hi;

        uint32_t pa[8], pb[8];
        #pragma unroll
        for (int nn = 0; nn < 8; nn++) {
            float p0 = __expf(s[nn][0] - mn_lo);
            float p1 = __expf(s[nn][1] - mn_lo);
            float p2 = __expf(s[nn][2] - mn_hi);
            float p3 = __expf(s[nn][3] - mn_hi);
            l_lo += p0 + p1;
            l_hi += p2 + p3;
            __half2 hA = __floats2half2_rn(p0, p1);
            __half2 hB = __floats2half2_rn(p2, p3);
            pa[nn] = *(uint32_t*)&hA;
            pb[nn] = *(uint32_t*)&hB;
            o[nn][0] *= sc_lo; o[nn][1] *= sc_lo;
            o[nn][2] *= sc_hi; o[nn][3] *= sc_hi;
        }

        // ---- PV: O += P * V (B frags via ldmatrix.trans on plain V[key][d]) ----
        #pragma unroll
        for (int kk = 0; kk < 4; kk++) {
            uint32_t a[4] = { pa[2 * kk], pb[2 * kk], pa[2 * kk + 1], pb[2 * kk + 1] };
            #pragma unroll
            for (int nn = 0; nn < 8; nn++) {
                uint32_t bv[2];
                ldx2t(bv, sb + (uint32_t)(vs + (kk * 16 + l15) * STR + nn * 8) * 2);
                mma16816(o[nn], a, bv);
            }
        }
    }

    // ---- epilogue: reduce l across lane%4, normalize, store ----
    l_lo += __shfl_xor_sync(0xffffffffu, l_lo, 1);
    l_lo += __shfl_xor_sync(0xffffffffu, l_lo, 2);
    l_hi += __shfl_xor_sync(0xffffffffu, l_hi, 1);
    l_hi += __shfl_xor_sync(0xffffffffu, l_hi, 2);
    const float inv_lo = 1.0f / l_lo;
    const float inv_hi = 1.0f / l_hi;

    const int r_lo = wid * 16 + (lane >> 2);
    const int r_hi = r_lo + 8;
    #pragma unroll
    for (int nn = 0; nn < 8; nn++) {
        int d0 = nn * 8 + (lane & 3) * 2;
        float2 wlo = { o[nn][0] * inv_lo, o[nn][1] * inv_lo };
        float2 whi = { o[nn][2] * inv_hi, o[nn][3] * inv_hi };
        *(float2*)(Og + (long long)r_lo * DHD + d0) = wlo;
        *(float2*)(Og + (long long)r_hi * DHD + d0) = whi;
    }
}

extern "C" void kernel_launch(void* const* d_in, const int* in_sizes, int n_in,
                              void* d_out, int out_size) {
    const float* Q = (const float*)d_in[0];
    const float* K = (const float*)d_in[1];
    const float* V = (const float*)d_in[2];
    float* O = (float*)d_out;

    const int BH = in_sizes[0] / (S_LEN * DHD);  // 64

    preconv_kernel<<<(unsigned)(TOTE / 4 / 256), 256>>>(K, V);

    cudaFuncSetAttribute(attn_mma_kernel,
                         cudaFuncAttributeMaxDynamicSharedMemorySize, SMEM_BYTES);
    dim3 grid(S_LEN / BM, BH);
    attn_mma_kernel<<<grid, 256, SMEM_BYTES>>>(Q, O);
}

// round 8
// speedup vs baseline: 5.8680x; 1.2554x over previous
#include <cuda_runtime.h>
#include <cuda_fp16.h>
#include <cstdint>

// Attention O = softmax(QK^T)V, [B=4,H=16,S=2048,D=64], fp32.
// R7: 2-pass QK^T:  S = Qh*Kh + Ql*Kh  (= full-precision Q times fp16 K).
// K residual pass dropped: -25% tensor MACs, -20% L1, smaller smem/preconv.
// K/V preconverted to fp16 scratch; cp.async double-buffered mainloop.

#define S_LEN 2048
#define DHD 64
#define BM 128
#define BN 64
#define NT (S_LEN / BN)     // 32
#define STR 72              // smem row stride in halfs
#define TOTE (64LL * S_LEN * DHD)   // elements per tensor (BH=64)

// smem offsets (halfs)
#define O_QH 0
#define O_QL (BM * STR)                 // 9216
#define O_B0 (2 * BM * STR)             // 18432
#define BUFH (2 * BN * STR)             // 9216 halfs per buffer (KH,VS)
#define SMEM_HALFS (O_B0 + 2 * BUFH)    // 36864
#define SMEM_BYTES (SMEM_HALFS * 2)     // 73728

__device__ __half g_KH[TOTE];
__device__ __half g_VS[TOTE];

static __device__ __forceinline__ uint32_t sa(const void* p) {
    uint32_t a;
    asm("{\n\t.reg .u64 t;\n\tcvta.to.shared.u64 t, %1;\n\tcvt.u32.u64 %0, t;\n\t}"
        : "=r"(a) : "l"(p));
    return a;
}
static __device__ __forceinline__ void ldx4(uint32_t* r, uint32_t a) {
    asm volatile("ldmatrix.sync.aligned.m8n8.x4.shared.b16 {%0,%1,%2,%3}, [%4];"
                 : "=r"(r[0]), "=r"(r[1]), "=r"(r[2]), "=r"(r[3]) : "r"(a));
}
static __device__ __forceinline__ void ldx2(uint32_t* r, uint32_t a) {
    asm volatile("ldmatrix.sync.aligned.m8n8.x2.shared.b16 {%0,%1}, [%2];"
                 : "=r"(r[0]), "=r"(r[1]) : "r"(a));
}
static __device__ __forceinline__ void ldx2t(uint32_t* r, uint32_t a) {
    asm volatile("ldmatrix.sync.aligned.m8n8.x2.trans.shared.b16 {%0,%1}, [%2];"
                 : "=r"(r[0]), "=r"(r[1]) : "r"(a));
}
static __device__ __forceinline__ void mma16816(float* d, const uint32_t* a, const uint32_t* b) {
    asm volatile("mma.sync.aligned.m16n8k16.row.col.f32.f16.f16.f32 "
                 "{%0,%1,%2,%3},{%4,%5,%6,%7},{%8,%9},{%0,%1,%2,%3};"
                 : "+f"(d[0]), "+f"(d[1]), "+f"(d[2]), "+f"(d[3])
                 : "r"(a[0]), "r"(a[1]), "r"(a[2]), "r"(a[3]), "r"(b[0]), "r"(b[1]));
}
static __device__ __forceinline__ void cpasync16(uint32_t dst, const void* src) {
    asm volatile("cp.async.cg.shared.global [%0], [%1], 16;" :: "r"(dst), "l"(src) : "memory");
}
#define CP_COMMIT() asm volatile("cp.async.commit_group;" ::: "memory")
#define CP_WAIT0()  asm volatile("cp.async.wait_group 0;" ::: "memory")

// split (a,b) into packed hi half2 and residual-lo half2
static __device__ __forceinline__ void split2(float a, float b, uint32_t& hi, uint32_t& lo) {
    __half ha = __float2half_rn(a), hb = __float2half_rn(b);
    __half2 h = __halves2half2(ha, hb);
    __half2 l = __floats2half2_rn(a - __half2float(ha), b - __half2float(hb));
    hi = *(uint32_t*)&h;
    lo = *(uint32_t*)&l;
}

// ---- pass 1: K,V fp32 -> fp16 scratch ----
__global__ void __launch_bounds__(256)
preconv_kernel(const float* __restrict__ K, const float* __restrict__ V) {
    long long i4 = ((long long)blockIdx.x * 256 + threadIdx.x) * 4;
    if (i4 >= TOTE) return;
    float4 k4 = *(const float4*)(K + i4);
    float4 v4 = *(const float4*)(V + i4);
    __half2 ka = __floats2half2_rn(k4.x, k4.y);
    __half2 kb = __floats2half2_rn(k4.z, k4.w);
    *(uint32_t*)(g_KH + i4)     = *(uint32_t*)&ka;
    *(uint32_t*)(g_KH + i4 + 2) = *(uint32_t*)&kb;
    __half2 va = __floats2half2_rn(v4.x, v4.y);
    __half2 vb = __floats2half2_rn(v4.z, v4.w);
    *(uint32_t*)(g_VS + i4)     = *(uint32_t*)&va;
    *(uint32_t*)(g_VS + i4 + 2) = *(uint32_t*)&vb;
}

// ---- pass 2: flash attention ----
__global__ void __launch_bounds__(256, 2)
attn_mma_kernel(const float* __restrict__ Q, float* __restrict__ Out)
{
    extern __shared__ __half sm[];
    const uint32_t sb = sa(sm);

    const int tid  = threadIdx.x;
    const int wid  = tid >> 5;
    const int lane = tid & 31;
    const int l15  = lane & 15;

    const long long base = (long long)blockIdx.y * (S_LEN * DHD);
    const float*  Qg  = Q + base + (long long)blockIdx.x * (BM * DHD);
    const __half* KHg = g_KH + base;
    const __half* VSg = g_VS + base;
    float*        Og  = Out + base + (long long)blockIdx.x * (BM * DHD);

    // cp.async chunk mapping: 2 chunks per thread per matrix (512 chunks each)
    const int c0r = tid >> 3, c0c = (tid & 7) * 8;          // chunk tid
    const int c1r = (tid + 256) >> 3, c1c = c0c;            // chunk tid+256

    // ---- prologue: issue tile-0 copies, then convert Q ----
    {
        uint32_t bk = sb + (uint32_t)(O_B0) * 2;
        cpasync16(bk + (uint32_t)(c0r * STR + c0c) * 2, KHg + c0r * DHD + c0c);
        cpasync16(bk + (uint32_t)(c1r * STR + c1c) * 2, KHg + c1r * DHD + c1c);
        bk += BN * STR * 2;
        cpasync16(bk + (uint32_t)(c0r * STR + c0c) * 2, VSg + c0r * DHD + c0c);
        cpasync16(bk + (uint32_t)(c1r * STR + c1c) * 2, VSg + c1r * DHD + c1c);
        CP_COMMIT();
    }

    #pragma unroll
    for (int i = 0; i < 8; i++) {
        int idx = tid * 4 + i * 1024;     // 0..8191
        int r = idx >> 6, c = idx & 63;
        float4 q = *(const float4*)(Qg + r * DHD + c);
        uint32_t h0, l0, h1, l1;
        split2(q.x, q.y, h0, l0);
        split2(q.z, q.w, h1, l1);
        *(uint32_t*)(&sm[O_QH + r * STR + c])     = h0;
        *(uint32_t*)(&sm[O_QH + r * STR + c + 2]) = h1;
        *(uint32_t*)(&sm[O_QL + r * STR + c])     = l0;
        *(uint32_t*)(&sm[O_QL + r * STR + c + 2]) = l1;
    }

    float o[8][4];
    #pragma unroll
    for (int nn = 0; nn < 8; nn++)
        #pragma unroll
        for (int j = 0; j < 4; j++) o[nn][j] = 0.0f;
    float m_lo = -1.0e30f, m_hi = -1.0e30f, l_lo = 0.0f, l_hi = 0.0f;

    for (int t = 0; t < NT; t++) {
        CP_WAIT0();            // tile t landed (only group outstanding)
        __syncthreads();       // collective: tile t visible; buffer swap safe

        // issue tile t+1 into the other buffer (overlaps compute below)
        if (t + 1 < NT) {
            const long long kg = (long long)(t + 1) * BN * DHD;
            uint32_t bk = sb + (uint32_t)(O_B0 + ((t + 1) & 1) * BUFH) * 2;
            cpasync16(bk + (uint32_t)(c0r * STR + c0c) * 2, KHg + kg + c0r * DHD + c0c);
            cpasync16(bk + (uint32_t)(c1r * STR + c1c) * 2, KHg + kg + c1r * DHD + c1c);
            bk += BN * STR * 2;
            cpasync16(bk + (uint32_t)(c0r * STR + c0c) * 2, VSg + kg + c0r * DHD + c0c);
            cpasync16(bk + (uint32_t)(c1r * STR + c1c) * 2, VSg + kg + c1r * DHD + c1c);
            CP_COMMIT();
        }

        const int kh = O_B0 + (t & 1) * BUFH;
        const int vs = kh + BN * STR;

        // ---- QK^T: 2-pass (Qh*Kh + Ql*Kh = Q * fp16(K)) ----
        float s[8][4];
        #pragma unroll
        for (int nn = 0; nn < 8; nn++)
            #pragma unroll
            for (int j = 0; j < 4; j++) s[nn][j] = 0.0f;

        #pragma unroll
        for (int kk = 0; kk < 4; kk++) {
            const int ar = wid * 16 + (lane & 7) + ((lane >> 3) & 1) * 8;
            const int ac = kk * 16 + (lane >> 4) * 8;
            uint32_t ah[4], al[4];
            ldx4(ah, sb + (uint32_t)(O_QH + ar * STR + ac) * 2);
            ldx4(al, sb + (uint32_t)(O_QL + ar * STR + ac) * 2);
            const int bro = (l15 & 7);
            const int bc  = kk * 16 + ((l15 >> 3) & 1) * 8;
            #pragma unroll
            for (int nn = 0; nn < 8; nn++) {
                uint32_t bh[2];
                ldx2(bh, sb + (uint32_t)(kh + (nn * 8 + bro) * STR + bc) * 2);
                mma16816(s[nn], ah, bh);
                mma16816(s[nn], al, bh);
            }
        }

        // ---- online softmax (rows: lo = lane>>2, hi = +8) ----
        float mt_lo = -1.0e30f, mt_hi = -1.0e30f;
        #pragma unroll
        for (int nn = 0; nn < 8; nn++) {
            mt_lo = fmaxf(mt_lo, fmaxf(s[nn][0], s[nn][1]));
            mt_hi = fmaxf(mt_hi, fmaxf(s[nn][2], s[nn][3]));
        }
        mt_lo = fmaxf(mt_lo, __shfl_xor_sync(0xffffffffu, mt_lo, 1));
        mt_lo = fmaxf(mt_lo, __shfl_xor_sync(0xffffffffu, mt_lo, 2));
        mt_hi = fmaxf(mt_hi, __shfl_xor_sync(0xffffffffu, mt_hi, 1));
        mt_hi = fmaxf(mt_hi, __shfl_xor_sync(0xffffffffu, mt_hi, 2));

        const float mn_lo = fmaxf(m_lo, mt_lo);
        const float mn_hi = fmaxf(m_hi, mt_hi);
        const float sc_lo = __expf(m_lo - mn_lo);
        const float sc_hi = __expf(m_hi - mn_hi);
        m_lo = mn_lo; m_hi = mn_hi;
        l_lo *= sc_lo; l_hi *= sc_hi;

        uint32_t pa[8], pb[8];
        #pragma unroll
        for (int nn = 0; nn < 8; nn++) {
            float p0 = __expf(s[nn][0] - mn_lo);
            float p1 = __expf(s[nn][1] - mn_lo);
            float p2 = __expf(s[nn][2] - mn_hi);
            float p3 = __expf(s[nn][3] - mn_hi);
            l_lo += p0 + p1;
            l_hi += p2 + p3;
            __half2 hA = __floats2half2_rn(p0, p1);
            __half2 hB = __floats2half2_rn(p2, p3);
            pa[nn] = *(uint32_t*)&hA;
            pb[nn] = *(uint32_t*)&hB;
            o[nn][0] *= sc_lo; o[nn][1] *= sc_lo;
            o[nn][2] *= sc_hi; o[nn][3] *= sc_hi;
        }

        // ---- PV: O += P * V (B frags via ldmatrix.trans on plain V[key][d]) ----
        #pragma unroll
        for (int kk = 0; kk < 4; kk++) {
            uint32_t a[4] = { pa[2 * kk], pb[2 * kk], pa[2 * kk + 1], pb[2 * kk + 1] };
            #pragma unroll
            for (int nn = 0; nn < 8; nn++) {
                uint32_t bv[2];
                ldx2t(bv, sb + (uint32_t)(vs + (kk * 16 + l15) * STR + nn * 8) * 2);
                mma16816(o[nn], a, bv);
            }
        }
    }

    // ---- epilogue: reduce l across lane%4, normalize, store ----
    l_lo += __shfl_xor_sync(0xffffffffu, l_lo, 1);
    l_lo += __shfl_xor_sync(0xffffffffu, l_lo, 2);
    l_hi += __shfl_xor_sync(0xffffffffu, l_hi, 1);
    l_hi += __shfl_xor_sync(0xffffffffu, l_hi, 2);
    const float inv_lo = 1.0f / l_lo;
    const float inv_hi = 1.0f / l_hi;

    const int r_lo = wid * 16 + (lane >> 2);
    const int r_hi = r_lo + 8;
    #pragma unroll
    for (int nn = 0; nn < 8; nn++) {
        int d0 = nn * 8 + (lane & 3) * 2;
        float2 wlo = { o[nn][0] * inv_lo, o[nn][1] * inv_lo };
        float2 whi = { o[nn][2] * inv_hi, o[nn][3] * inv_hi };
        *(float2*)(Og + (long long)r_lo * DHD + d0) = wlo;
        *(float2*)(Og + (long long)r_hi * DHD + d0) = whi;
    }
}

extern "C" void kernel_launch(void* const* d_in, const int* in_sizes, int n_in,
                              void* d_out, int out_size) {
    const float* Q = (const float*)d_in[0];
    const float* K = (const float*)d_in[1];
    const float* V = (const float*)d_in[2];
    float* O = (float*)d_out;

    const int BH = in_sizes[0] / (S_LEN * DHD);  // 64

    preconv_kernel<<<(unsigned)(TOTE / 4 / 256), 256>>>(K, V);

    cudaFuncSetAttribute(attn_mma_kernel,
                         cudaFuncAttributeMaxDynamicSharedMemorySize, SMEM_BYTES);
    dim3 grid(S_LEN / BM, BH);
    attn_mma_kernel<<<grid, 256, SMEM_BYTES>>>(Q, O);
}

// round 9
// speedup vs baseline: 6.1895x; 1.0548x over previous
#include <cuda_runtime.h>
#include <cuda_fp16.h>
#include <cstdint>

// Attention O = softmax(QK^T)V, [B=4,H=16,S=2048,D=64], fp32.
// R8: log2e folded into Q (softmax uses raw ex2, no per-element FMUL);
//     K/V fragment loads via ldmatrix.x4 (half the LDSM instr + addr math).
// 2-pass QK^T (Qh*Kh + Ql*Kh), fp16 PV, cp.async double-buffered.

#define S_LEN 2048
#define DHD 64
#define BM 128
#define BN 64
#define NT (S_LEN / BN)     // 32
#define STR 72              // smem row stride in halfs
#define TOTE (64LL * S_LEN * DHD)   // elements per tensor (BH=64)
#define LOG2E 1.44269504088896340736f

// smem offsets (halfs)
#define O_QH 0
#define O_QL (BM * STR)                 // 9216
#define O_B0 (2 * BM * STR)             // 18432
#define BUFH (2 * BN * STR)             // 9216 halfs per buffer (KH,VS)
#define SMEM_HALFS (O_B0 + 2 * BUFH)    // 36864
#define SMEM_BYTES (SMEM_HALFS * 2)     // 73728

__device__ __half g_KH[TOTE];
__device__ __half g_VS[TOTE];

static __device__ __forceinline__ uint32_t sa(const void* p) {
    uint32_t a;
    asm("{\n\t.reg .u64 t;\n\tcvta.to.shared.u64 t, %1;\n\tcvt.u32.u64 %0, t;\n\t}"
        : "=r"(a) : "l"(p));
    return a;
}
static __device__ __forceinline__ float ex2(float x) {
    float r;
    asm("ex2.approx.f32 %0, %1;" : "=f"(r) : "f"(x));
    return r;
}
static __device__ __forceinline__ void ldx4(uint32_t* r, uint32_t a) {
    asm volatile("ldmatrix.sync.aligned.m8n8.x4.shared.b16 {%0,%1,%2,%3}, [%4];"
                 : "=r"(r[0]), "=r"(r[1]), "=r"(r[2]), "=r"(r[3]) : "r"(a));
}
static __device__ __forceinline__ void ldx4t(uint32_t* r, uint32_t a) {
    asm volatile("ldmatrix.sync.aligned.m8n8.x4.trans.shared.b16 {%0,%1,%2,%3}, [%4];"
                 : "=r"(r[0]), "=r"(r[1]), "=r"(r[2]), "=r"(r[3]) : "r"(a));
}
static __device__ __forceinline__ void mma16816(float* d, const uint32_t* a, const uint32_t* b) {
    asm volatile("mma.sync.aligned.m16n8k16.row.col.f32.f16.f16.f32 "
                 "{%0,%1,%2,%3},{%4,%5,%6,%7},{%8,%9},{%0,%1,%2,%3};"
                 : "+f"(d[0]), "+f"(d[1]), "+f"(d[2]), "+f"(d[3])
                 : "r"(a[0]), "r"(a[1]), "r"(a[2]), "r"(a[3]), "r"(b[0]), "r"(b[1]));
}
static __device__ __forceinline__ void cpasync16(uint32_t dst, const void* src) {
    asm volatile("cp.async.cg.shared.global [%0], [%1], 16;" :: "r"(dst), "l"(src) : "memory");
}
#define CP_COMMIT() asm volatile("cp.async.commit_group;" ::: "memory")
#define CP_WAIT0()  asm volatile("cp.async.wait_group 0;" ::: "memory")

// split (a,b) into packed hi half2 and residual-lo half2
static __device__ __forceinline__ void split2(float a, float b, uint32_t& hi, uint32_t& lo) {
    __half ha = __float2half_rn(a), hb = __float2half_rn(b);
    __half2 h = __halves2half2(ha, hb);
    __half2 l = __floats2half2_rn(a - __half2float(ha), b - __half2float(hb));
    hi = *(uint32_t*)&h;
    lo = *(uint32_t*)&l;
}

// ---- pass 1: K,V fp32 -> fp16 scratch ----
__global__ void __launch_bounds__(256)
preconv_kernel(const float* __restrict__ K, const float* __restrict__ V) {
    long long i4 = ((long long)blockIdx.x * 256 + threadIdx.x) * 4;
    if (i4 >= TOTE) return;
    float4 k4 = *(const float4*)(K + i4);
    float4 v4 = *(const float4*)(V + i4);
    __half2 ka = __floats2half2_rn(k4.x, k4.y);
    __half2 kb = __floats2half2_rn(k4.z, k4.w);
    *(uint32_t*)(g_KH + i4)     = *(uint32_t*)&ka;
    *(uint32_t*)(g_KH + i4 + 2) = *(uint32_t*)&kb;
    __half2 va = __floats2half2_rn(v4.x, v4.y);
    __half2 vb = __floats2half2_rn(v4.z, v4.w);
    *(uint32_t*)(g_VS + i4)     = *(uint32_t*)&va;
    *(uint32_t*)(g_VS + i4 + 2) = *(uint32_t*)&vb;
}

// ---- pass 2: flash attention ----
__global__ void __launch_bounds__(256, 2)
attn_mma_kernel(const float* __restrict__ Q, float* __restrict__ Out)
{
    extern __shared__ __half sm[];
    const uint32_t sb = sa(sm);

    const int tid  = threadIdx.x;
    const int wid  = tid >> 5;
    const int lane = tid & 31;
    const int l15  = lane & 15;

    const long long base = (long long)blockIdx.y * (S_LEN * DHD);
    const float*  Qg  = Q + base + (long long)blockIdx.x * (BM * DHD);
    const __half* KHg = g_KH + base;
    const __half* VSg = g_VS + base;
    float*        Og  = Out + base + (long long)blockIdx.x * (BM * DHD);

    // cp.async chunk mapping: 2 chunks per thread per matrix (512 chunks each)
    const int c0r = tid >> 3, c0c = (tid & 7) * 8;          // chunk tid
    const int c1r = (tid + 256) >> 3, c1c = c0c;            // chunk tid+256

    // ---- prologue: issue tile-0 copies, then convert Q (scaled by log2e) ----
    {
        uint32_t bk = sb + (uint32_t)(O_B0) * 2;
        cpasync16(bk + (uint32_t)(c0r * STR + c0c) * 2, KHg + c0r * DHD + c0c);
        cpasync16(bk + (uint32_t)(c1r * STR + c1c) * 2, KHg + c1r * DHD + c1c);
        bk += BN * STR * 2;
        cpasync16(bk + (uint32_t)(c0r * STR + c0c) * 2, VSg + c0r * DHD + c0c);
        cpasync16(bk + (uint32_t)(c1r * STR + c1c) * 2, VSg + c1r * DHD + c1c);
        CP_COMMIT();
    }

    #pragma unroll
    for (int i = 0; i < 8; i++) {
        int idx = tid * 4 + i * 1024;     // 0..8191
        int r = idx >> 6, c = idx & 63;
        float4 q = *(const float4*)(Qg + r * DHD + c);
        q.x *= LOG2E; q.y *= LOG2E; q.z *= LOG2E; q.w *= LOG2E;
        uint32_t h0, l0, h1, l1;
        split2(q.x, q.y, h0, l0);
        split2(q.z, q.w, h1, l1);
        *(uint32_t*)(&sm[O_QH + r * STR + c])     = h0;
        *(uint32_t*)(&sm[O_QH + r * STR + c + 2]) = h1;
        *(uint32_t*)(&sm[O_QL + r * STR + c])     = l0;
        *(uint32_t*)(&sm[O_QL + r * STR + c + 2]) = l1;
    }

    float o[8][4];
    #pragma unroll
    for (int nn = 0; nn < 8; nn++)
        #pragma unroll
        for (int j = 0; j < 4; j++) o[nn][j] = 0.0f;
    float m_lo = -1.0e30f, m_hi = -1.0e30f, l_lo = 0.0f, l_hi = 0.0f;

    for (int t = 0; t < NT; t++) {
        CP_WAIT0();            // tile t landed (only group outstanding)
        __syncthreads();       // collective: tile t visible; buffer swap safe

        // issue tile t+1 into the other buffer (overlaps compute below)
        if (t + 1 < NT) {
            const long long kg = (long long)(t + 1) * BN * DHD;
            uint32_t bk = sb + (uint32_t)(O_B0 + ((t + 1) & 1) * BUFH) * 2;
            cpasync16(bk + (uint32_t)(c0r * STR + c0c) * 2, KHg + kg + c0r * DHD + c0c);
            cpasync16(bk + (uint32_t)(c1r * STR + c1c) * 2, KHg + kg + c1r * DHD + c1c);
            bk += BN * STR * 2;
            cpasync16(bk + (uint32_t)(c0r * STR + c0c) * 2, VSg + kg + c0r * DHD + c0c);
            cpasync16(bk + (uint32_t)(c1r * STR + c1c) * 2, VSg + kg + c1r * DHD + c1c);
            CP_COMMIT();
        }

        const int kh = O_B0 + (t & 1) * BUFH;
        const int vs = kh + BN * STR;

        // ---- QK^T: 2-pass (Qh*Kh + Ql*Kh = Q * fp16(K)), log2 domain ----
        float s[8][4];
        #pragma unroll
        for (int nn = 0; nn < 8; nn++)
            #pragma unroll
            for (int j = 0; j < 4; j++) s[nn][j] = 0.0f;

        #pragma unroll
        for (int kk = 0; kk < 4; kk++) {
            const int ar = wid * 16 + (lane & 7) + ((lane >> 3) & 1) * 8;
            const int ac = kk * 16 + (lane >> 4) * 8;
            uint32_t ah[4], al[4];
            ldx4(ah, sb + (uint32_t)(O_QH + ar * STR + ac) * 2);
            ldx4(al, sb + (uint32_t)(O_QL + ar * STR + ac) * 2);
            // K fragment pair via x4: lanes 0-15 -> frag nn, 16-31 -> frag nn+1
            const int kr = (lane & 7) + ((lane >> 4) & 1) * 8;
            const int kc = kk * 16 + ((lane >> 3) & 1) * 8;
            #pragma unroll
            for (int nn = 0; nn < 8; nn += 2) {
                uint32_t bh4[4];
                ldx4(bh4, sb + (uint32_t)(kh + (nn * 8 + kr) * STR + kc) * 2);
                mma16816(s[nn],     ah, bh4);
                mma16816(s[nn],     al, bh4);
                mma16816(s[nn + 1], ah, bh4 + 2);
                mma16816(s[nn + 1], al, bh4 + 2);
            }
        }

        // ---- online softmax in log2 domain (rows: lo = lane>>2, hi = +8) ----
        float mt_lo = -1.0e30f, mt_hi = -1.0e30f;
        #pragma unroll
        for (int nn = 0; nn < 8; nn++) {
            mt_lo = fmaxf(mt_lo, fmaxf(s[nn][0], s[nn][1]));
            mt_hi = fmaxf(mt_hi, fmaxf(s[nn][2], s[nn][3]));
        }
        mt_lo = fmaxf(mt_lo, __shfl_xor_sync(0xffffffffu, mt_lo, 1));
        mt_lo = fmaxf(mt_lo, __shfl_xor_sync(0xffffffffu, mt_lo, 2));
        mt_hi = fmaxf(mt_hi, __shfl_xor_sync(0xffffffffu, mt_hi, 1));
        mt_hi = fmaxf(mt_hi, __shfl_xor_sync(0xffffffffu, mt_hi, 2));

        const float mn_lo = fmaxf(m_lo, mt_lo);
        const float mn_hi = fmaxf(m_hi, mt_hi);
        const float sc_lo = ex2(m_lo - mn_lo);
        const float sc_hi = ex2(m_hi - mn_hi);
        m_lo = mn_lo; m_hi = mn_hi;
        l_lo *= sc_lo; l_hi *= sc_hi;

        uint32_t pa[8], pb[8];
        #pragma unroll
        for (int nn = 0; nn < 8; nn++) {
            float p0 = ex2(s[nn][0] - mn_lo);
            float p1 = ex2(s[nn][1] - mn_lo);
            float p2 = ex2(s[nn][2] - mn_hi);
            float p3 = ex2(s[nn][3] - mn_hi);
            l_lo += p0 + p1;
            l_hi += p2 + p3;
            __half2 hA = __floats2half2_rn(p0, p1);
            __half2 hB = __floats2half2_rn(p2, p3);
            pa[nn] = *(uint32_t*)&hA;
            pb[nn] = *(uint32_t*)&hB;
            o[nn][0] *= sc_lo; o[nn][1] *= sc_lo;
            o[nn][2] *= sc_hi; o[nn][3] *= sc_hi;
        }

        // ---- PV: O += P * V (B frag pairs via ldmatrix.x4.trans) ----
        #pragma unroll
        for (int kk = 0; kk < 4; kk++) {
            uint32_t a[4] = { pa[2 * kk], pb[2 * kk], pa[2 * kk + 1], pb[2 * kk + 1] };
            // lanes 0-15 -> d-cols nn*8.., lanes 16-31 -> d-cols nn*8+8..
            const int vr = kk * 16 + l15;
            const int vc = ((lane >> 4) & 1) * 8;
            #pragma unroll
            for (int nn = 0; nn < 8; nn += 2) {
                uint32_t bv4[4];
                ldx4t(bv4, sb + (uint32_t)(vs + vr * STR + nn * 8 + vc) * 2);
                mma16816(o[nn],     a, bv4);
                mma16816(o[nn + 1], a, bv4 + 2);
            }
        }
    }

    // ---- epilogue: reduce l across lane%4, normalize, store ----
    l_lo += __shfl_xor_sync(0xffffffffu, l_lo, 1);
    l_lo += __shfl_xor_sync(0xffffffffu, l_lo, 2);
    l_hi += __shfl_xor_sync(0xffffffffu, l_hi, 1);
    l_hi += __shfl_xor_sync(0xffffffffu, l_hi, 2);
    const float inv_lo = 1.0f / l_lo;
    const float inv_hi = 1.0f / l_hi;

    const int r_lo = wid * 16 + (lane >> 2);
    const int r_hi = r_lo + 8;
    #pragma unroll
    for (int nn = 0; nn < 8; nn++) {
        int d0 = nn * 8 + (lane & 3) * 2;
        float2 wlo = { o[nn][0] * inv_lo, o[nn][1] * inv_lo };
        float2 whi = { o[nn][2] * inv_hi, o[nn][3] * inv_hi };
        *(float2*)(Og + (long long)r_lo * DHD + d0) = wlo;
        *(float2*)(Og + (long long)r_hi * DHD + d0) = whi;
    }
}

extern "C" void kernel_launch(void* const* d_in, const int* in_sizes, int n_in,
                              void* d_out, int out_size) {
    const float* Q = (const float*)d_in[0];
    const float* K = (const float*)d_in[1];
    const float* V = (const float*)d_in[2];
    float* O = (float*)d_out;

    const int BH = in_sizes[0] / (S_LEN * DHD);  // 64

    preconv_kernel<<<(unsigned)(TOTE / 4 / 256), 256>>>(K, V);

    cudaFuncSetAttribute(attn_mma_kernel,
                         cudaFuncAttributeMaxDynamicSharedMemorySize, SMEM_BYTES);
    dim3 grid(S_LEN / BM, BH);
    attn_mma_kernel<<<grid, 256, SMEM_BYTES>>>(Q, O);
}